// round 2
// baseline (speedup 1.0000x reference)
#include <cuda_runtime.h>
#include <cstdint>

// Problem shape (fixed by the dataset)
#define B 64
#define S 512
#define D 512

// ---------------- scratch (no allocations allowed) ----------------
__device__ float g_n1[(size_t)B * S * D];   // normalized emb1
__device__ float g_n2[(size_t)B * S * D];   // normalized emb2
__device__ int   g_rowmax[B * S];           // ordered-int encoded float max
__device__ int   g_colmax[B * S];

// ---------------- helpers ----------------
__device__ __forceinline__ int ordf(float f) {
    int i = __float_as_int(f);
    return (i >= 0) ? i : (i ^ 0x7FFFFFFF);
}
__device__ __forceinline__ float deord(int s) {
    return __int_as_float((s >= 0) ? s : (s ^ 0x7FFFFFFF));
}

__device__ __forceinline__ unsigned long long pack2(float lo, float hi) {
    unsigned long long r;
    asm("mov.b64 %0, {%1, %2};" : "=l"(r) : "f"(lo), "f"(hi));
    return r;
}
__device__ __forceinline__ void unpack2(unsigned long long v, float& lo, float& hi) {
    asm("mov.b64 {%0, %1}, %2;" : "=f"(lo), "=f"(hi) : "l"(v));
}
__device__ __forceinline__ unsigned long long fma2(unsigned long long a,
                                                   unsigned long long b,
                                                   unsigned long long c) {
    unsigned long long d;
    asm("fma.rn.f32x2 %0, %1, %2, %3;" : "=l"(d) : "l"(a), "l"(b), "l"(c));
    return d;
}

// ---------------- kernel 1: L2 normalize rows of [B*S, D] ----------------
__global__ void k_norm(const float* __restrict__ in, float* __restrict__ out) {
    int row  = (blockIdx.x * blockDim.x + threadIdx.x) >> 5;
    int lane = threadIdx.x & 31;
    if (row >= B * S) return;
    const float4* rp = (const float4*)(in + (size_t)row * D);
    float4*       wp = (float4*)(out + (size_t)row * D);

    float4 v[4];
    float s = 0.f;
#pragma unroll
    for (int r = 0; r < 4; r++) {
        v[r] = rp[lane + 32 * r];
        s = fmaf(v[r].x, v[r].x, s);
        s = fmaf(v[r].y, v[r].y, s);
        s = fmaf(v[r].z, v[r].z, s);
        s = fmaf(v[r].w, v[r].w, s);
    }
#pragma unroll
    for (int o = 16; o > 0; o >>= 1) s += __shfl_xor_sync(0xFFFFFFFFu, s, o);
    float inv = 1.0f / fmaxf(sqrtf(s), 1e-8f);
#pragma unroll
    for (int r = 0; r < 4; r++) {
        float4 w = v[r];
        w.x *= inv; w.y *= inv; w.z *= inv; w.w *= inv;
        wp[lane + 32 * r] = w;
    }
}

// ---------------- kernel 2: init max buffers ----------------
__global__ void k_init(int neg) {
    int i = blockIdx.x * blockDim.x + threadIdx.x;
    if (i < B * S) { g_rowmax[i] = neg; g_colmax[i] = neg; }
}

// ---------------- kernel 3: tiled sim + masked row/col max ----------------
// Block computes a 64(i) x 128(j) tile of sim[b] = e1[b] @ e2[b]^T.
// 16x16 threads, each owns 4 rows x 8 cols held as f32x2 pairs.
#define BI 64
#define BJ 128
#define KC 32
#define NEGF (-1e9f)

__global__ __launch_bounds__(256, 2) void k_sim(const int* __restrict__ mask1,
                                                const int* __restrict__ mask2) {
    __shared__ float As[KC * BI];        // swizzled [k][i]
    __shared__ float Bs[KC * BJ];        // swizzled [k][j]
    __shared__ float redR[BI][16];
    __shared__ float redC[BJ][16];

    const int b  = blockIdx.z;
    const int i0 = blockIdx.y * BI;
    const int j0 = blockIdx.x * BJ;
    const int tid = threadIdx.x;
    const int tx = tid & 15;
    const int ty = tid >> 4;

    const float* Ag = g_n1 + ((size_t)b * S + i0) * D;
    const float* Bg = g_n2 + ((size_t)b * S + j0) * D;

    unsigned long long acc[4][4];
#pragma unroll
    for (int r = 0; r < 4; r++)
#pragma unroll
        for (int p = 0; p < 4; p++) acc[r][p] = pack2(0.f, 0.f);

    for (int kc = 0; kc < D; kc += KC) {
        // fill A tile: global coalesced, swizzled smem store (conflict-free-ish)
        for (int t = tid; t < BI * KC; t += 256) {
            int i = t >> 5, k = t & 31;
            float v = Ag[(size_t)i * D + kc + k];
            int g = (i >> 2) ^ (k & 15);
            As[k * BI + 4 * g + (i & 3)] = v;
        }
        // fill B tile
        for (int t = tid; t < BJ * KC; t += 256) {
            int j = t >> 5, k = t & 31;
            float v = Bg[(size_t)j * D + kc + k];
            int g = (j >> 2) ^ k;
            Bs[k * BJ + 4 * g + (j & 3)] = v;
        }
        __syncthreads();

#pragma unroll
        for (int k = 0; k < KC; k++) {
            const float4 a4 = *(const float4*)(As + k * BI + 4 * (ty ^ (k & 15)));
            const float* bb = Bs + k * BJ;
            ulonglong2 bA = *(const ulonglong2*)(bb + 4 * ((2 * tx)     ^ k));
            ulonglong2 bB = *(const ulonglong2*)(bb + 4 * ((2 * tx + 1) ^ k));
            unsigned long long aa0 = pack2(a4.x, a4.x);
            unsigned long long aa1 = pack2(a4.y, a4.y);
            unsigned long long aa2 = pack2(a4.z, a4.z);
            unsigned long long aa3 = pack2(a4.w, a4.w);
            acc[0][0] = fma2(aa0, bA.x, acc[0][0]);
            acc[0][1] = fma2(aa0, bA.y, acc[0][1]);
            acc[0][2] = fma2(aa0, bB.x, acc[0][2]);
            acc[0][3] = fma2(aa0, bB.y, acc[0][3]);
            acc[1][0] = fma2(aa1, bA.x, acc[1][0]);
            acc[1][1] = fma2(aa1, bA.y, acc[1][1]);
            acc[1][2] = fma2(aa1, bB.x, acc[1][2]);
            acc[1][3] = fma2(aa1, bB.y, acc[1][3]);
            acc[2][0] = fma2(aa2, bA.x, acc[2][0]);
            acc[2][1] = fma2(aa2, bA.y, acc[2][1]);
            acc[2][2] = fma2(aa2, bB.x, acc[2][2]);
            acc[2][3] = fma2(aa2, bB.y, acc[2][3]);
            acc[3][0] = fma2(aa3, bA.x, acc[3][0]);
            acc[3][1] = fma2(aa3, bA.y, acc[3][1]);
            acc[3][2] = fma2(aa3, bB.x, acc[3][2]);
            acc[3][3] = fma2(aa3, bB.y, acc[3][3]);
        }
        __syncthreads();
    }

    // unpack to 4x8 floats
    float c[4][8];
#pragma unroll
    for (int r = 0; r < 4; r++)
#pragma unroll
        for (int p = 0; p < 4; p++) unpack2(acc[r][p], c[r][2 * p], c[r][2 * p + 1]);

    // masks for this thread's rows/cols
    int m1v[4], m2v[8];
#pragma unroll
    for (int r = 0; r < 4; r++) m1v[r] = mask1[b * S + i0 + ty * 4 + r];
#pragma unroll
    for (int q = 0; q < 8; q++) m2v[q] = mask2[b * S + j0 + tx * 8 + q];

    // per-thread row maxes (over valid j) and col maxes (over valid i)
#pragma unroll
    for (int r = 0; r < 4; r++) {
        float rm = NEGF;
#pragma unroll
        for (int q = 0; q < 8; q++)
            if (m2v[q]) rm = fmaxf(rm, c[r][q]);
        redR[ty * 4 + r][tx] = rm;
    }
#pragma unroll
    for (int q = 0; q < 8; q++) {
        float cm = NEGF;
#pragma unroll
        for (int r = 0; r < 4; r++)
            if (m1v[r]) cm = fmaxf(cm, c[r][q]);
        redC[tx * 8 + q][ty] = cm;
    }
    __syncthreads();

    if (tid < BI) {
        float m = NEGF;
#pragma unroll
        for (int t = 0; t < 16; t++) m = fmaxf(m, redR[tid][t]);
        atomicMax(&g_rowmax[b * S + i0 + tid], ordf(m));
    } else if (tid < BI + BJ) {
        int j = tid - BI;
        float m = NEGF;
#pragma unroll
        for (int t = 0; t < 16; t++) m = fmaxf(m, redC[j][t]);
        atomicMax(&g_colmax[b * S + j0 + j], ordf(m));
    }
}

// ---------------- kernel 4: final masked sums ----------------
__global__ void k_final(const int* __restrict__ mask1, const int* __restrict__ mask2,
                        float* __restrict__ out) {
    __shared__ float ssum[256];
    __shared__ int   scnt[256];
    const int b = blockIdx.x;
    const int tid = threadIdx.x;

    float s = 0.f;
    int   n = 0;
    for (int i = tid; i < S; i += 256) {
        int m1 = mask1[b * S + i];
        if (m1) s += deord(g_rowmax[b * S + i]);
        n += m1;
        int m2 = mask2[b * S + i];
        if (m2) s += deord(g_colmax[b * S + i]);
        n += m2;
    }
    ssum[tid] = s; scnt[tid] = n;
    __syncthreads();
    for (int o = 128; o > 0; o >>= 1) {
        if (tid < o) { ssum[tid] += ssum[tid + o]; scnt[tid] += scnt[tid + o]; }
        __syncthreads();
    }
    if (tid == 0) out[b] = ssum[0] / (float)scnt[0];
}

// ---------------- launch ----------------
extern "C" void kernel_launch(void* const* d_in, const int* in_sizes, int n_in,
                              void* d_out, int out_size) {
    const float* emb1  = (const float*)d_in[0];
    const float* emb2  = (const float*)d_in[1];
    const int*   mask1 = (const int*)d_in[2];
    const int*   mask2 = (const int*)d_in[3];
    float*       out   = (float*)d_out;

    float* n1p; float* n2p;
    cudaGetSymbolAddress((void**)&n1p, g_n1);
    cudaGetSymbolAddress((void**)&n2p, g_n2);

    // 1) normalize (B*S rows, one warp per row)
    k_norm<<<(B * S) / 8, 256>>>(emb1, n1p);
    k_norm<<<(B * S) / 8, 256>>>(emb2, n2p);

    // 2) init max buffers with ordered(-1e9)
    int neg = -1000000000; // computed on device instead for exactness:
    // ordf(-1e9f): bits of -1e9 = 0xCE6E6B28 (negative) -> ^0x7FFFFFFF = 0xB191 94D7
    neg = (int)0xB19194D7;
    k_init<<<(B * S + 255) / 256, 256>>>(neg);

    // 3) sim tiles: grid (j-tiles=4, i-tiles=8, batch=64)
    dim3 grid(S / BJ, S / BI, B);
    k_sim<<<grid, 256>>>(mask1, mask2);

    // 4) final
    k_final<<<B, 256>>>(mask1, mask2, out);
}

// round 3
// speedup vs baseline: 2.0252x; 2.0252x over previous
#include <cuda_runtime.h>
#include <cstdint>

// Problem shape (fixed by the dataset)
#define B 64
#define S 512
#define D 512

// ---------------- scratch (no allocations allowed) ----------------
__device__ float g_inv1[B * S];   // 1/||x_i||
__device__ float g_inv2[B * S];   // 1/||y_j||
__device__ int   g_rowmax[B * S]; // ordered-int encoded float max
__device__ int   g_colmax[B * S];

// ---------------- helpers ----------------
__device__ __forceinline__ int ordf(float f) {
    int i = __float_as_int(f);
    return (i >= 0) ? i : (i ^ 0x7FFFFFFF);
}
__device__ __forceinline__ float deord(int s) {
    return __int_as_float((s >= 0) ? s : (s ^ 0x7FFFFFFF));
}
__device__ __forceinline__ unsigned long long fma2(unsigned long long a,
                                                   unsigned long long b,
                                                   unsigned long long c) {
    unsigned long long d;
    asm("fma.rn.f32x2 %0, %1, %2, %3;" : "=l"(d) : "l"(a), "l"(b), "l"(c));
    return d;
}
__device__ __forceinline__ void unpack2(unsigned long long v, float& lo, float& hi) {
    asm("mov.b64 {%0, %1}, %2;" : "=f"(lo), "=f"(hi) : "l"(v));
}

// ---------------- kernel 1: inverse L2 norms of rows of [B*S, D] ----------------
__global__ void k_inv(const float* __restrict__ in, float* __restrict__ out) {
    int row  = (blockIdx.x * blockDim.x + threadIdx.x) >> 5;
    int lane = threadIdx.x & 31;
    if (row >= B * S) return;
    const float4* rp = (const float4*)(in + (size_t)row * D);
    float s = 0.f;
#pragma unroll
    for (int r = 0; r < 4; r++) {
        float4 v = rp[lane + 32 * r];
        s = fmaf(v.x, v.x, s);
        s = fmaf(v.y, v.y, s);
        s = fmaf(v.z, v.z, s);
        s = fmaf(v.w, v.w, s);
    }
#pragma unroll
    for (int o = 16; o > 0; o >>= 1) s += __shfl_xor_sync(0xFFFFFFFFu, s, o);
    if (lane == 0) out[row] = 1.0f / fmaxf(sqrtf(s), 1e-8f);
}

// ---------------- kernel 2: init max buffers ----------------
__global__ void k_init(int neg) {
    int i = blockIdx.x * blockDim.x + threadIdx.x;
    if (i < B * S) { g_rowmax[i] = neg; g_colmax[i] = neg; }
}

// ---------------- kernel 3: tiled sim + masked row/col max ----------------
// CTA of 128 threads (tx 0..7, ty 0..15) computes a 128(i) x 64(j) tile.
// Each thread owns rows i = 16r+ty (r<8) and cols j = 8q+tx (q<8).
// k-pair f32x2 accumulation: acc[r][q] holds (sum over even k, sum over odd k).
#define BI 128
#define BJ 64
#define KC 32
#define LDT 34          // smem row stride in floats (== 2 mod 32 -> conflict-free LDS.64)
#define NEGF (-1e9f)

__global__ __launch_bounds__(128, 2) void k_sim(
    const float* __restrict__ e1, const float* __restrict__ e2,
    const int* __restrict__ mask1, const int* __restrict__ mask2) {
    __shared__ float As[BI * LDT];
    __shared__ float Bs[BJ * LDT];
    __shared__ float redC[BJ][17];

    const int b  = blockIdx.z;
    const int i0 = blockIdx.y * BI;
    const int j0 = blockIdx.x * BJ;
    const int tid = threadIdx.x;
    const int tx = tid & 7;
    const int ty = tid >> 3;

    const float* Ag = e1 + ((size_t)b * S + i0) * D;
    const float* Bg = e2 + ((size_t)b * S + j0) * D;

    // fill-role indices: row fr (0..15, step 16), k-offset fk (float4 slot)
    const int fr = tid >> 3;
    const int fk = (tid & 7) * 4;

    // inverse norms for the rows this thread fills (same rows every chunk)
    float invA[8], invB[4];
#pragma unroll
    for (int p = 0; p < 8; p++) invA[p] = g_inv1[b * S + i0 + fr + 16 * p];
#pragma unroll
    for (int p = 0; p < 4; p++) invB[p] = g_inv2[b * S + j0 + fr + 16 * p];

    unsigned long long acc[8][8];
#pragma unroll
    for (int r = 0; r < 8; r++)
#pragma unroll
        for (int q = 0; q < 8; q++) acc[r][q] = 0ull;   // bits of (0.f, 0.f)

    for (int kc = 0; kc < D; kc += KC) {
        // A tile fill: 128 rows x 32 k, normalized on the fly
#pragma unroll
        for (int p = 0; p < 8; p++) {
            int i = fr + 16 * p;
            float4 v = *(const float4*)(Ag + (size_t)i * D + kc + fk);
            float s = invA[p];
            float2 lo = make_float2(v.x * s, v.y * s);
            float2 hi = make_float2(v.z * s, v.w * s);
            *(float2*)(As + i * LDT + fk)     = lo;
            *(float2*)(As + i * LDT + fk + 2) = hi;
        }
        // B tile fill: 64 rows x 32 k
#pragma unroll
        for (int p = 0; p < 4; p++) {
            int j = fr + 16 * p;
            float4 v = *(const float4*)(Bg + (size_t)j * D + kc + fk);
            float s = invB[p];
            float2 lo = make_float2(v.x * s, v.y * s);
            float2 hi = make_float2(v.z * s, v.w * s);
            *(float2*)(Bs + j * LDT + fk)     = lo;
            *(float2*)(Bs + j * LDT + fk + 2) = hi;
        }
        __syncthreads();

#pragma unroll 8
        for (int k = 0; k < KC; k += 2) {
            unsigned long long a[8], bb[8];
#pragma unroll
            for (int r = 0; r < 8; r++)
                a[r] = *(const unsigned long long*)(As + (16 * r + ty) * LDT + k);
#pragma unroll
            for (int q = 0; q < 8; q++)
                bb[q] = *(const unsigned long long*)(Bs + (8 * q + tx) * LDT + k);
#pragma unroll
            for (int r = 0; r < 8; r++)
#pragma unroll
                for (int q = 0; q < 8; q++)
                    acc[r][q] = fma2(a[r], bb[q], acc[r][q]);
        }
        __syncthreads();
    }

    // fold k-even + k-odd partial sums
    float c[8][8];
#pragma unroll
    for (int r = 0; r < 8; r++)
#pragma unroll
        for (int q = 0; q < 8; q++) {
            float lo, hi;
            unpack2(acc[r][q], lo, hi);
            c[r][q] = lo + hi;
        }

    // masks for this thread's rows/cols
    int m1v[8], m2v[8];
#pragma unroll
    for (int r = 0; r < 8; r++) m1v[r] = mask1[b * S + i0 + 16 * r + ty];
#pragma unroll
    for (int q = 0; q < 8; q++) m2v[q] = mask2[b * S + j0 + 8 * q + tx];

    // row maxes: reduce over the 8 tx lanes (same ty = consecutive lanes)
#pragma unroll
    for (int r = 0; r < 8; r++) {
        float rm = NEGF;
#pragma unroll
        for (int q = 0; q < 8; q++)
            if (m2v[q]) rm = fmaxf(rm, c[r][q]);
        rm = fmaxf(rm, __shfl_xor_sync(0xFFFFFFFFu, rm, 1));
        rm = fmaxf(rm, __shfl_xor_sync(0xFFFFFFFFu, rm, 2));
        rm = fmaxf(rm, __shfl_xor_sync(0xFFFFFFFFu, rm, 4));
        if (tx == 0) atomicMax(&g_rowmax[b * S + i0 + 16 * r + ty], ordf(rm));
    }

    // col maxes: cross-warp via smem
#pragma unroll
    for (int q = 0; q < 8; q++) {
        float cm = NEGF;
#pragma unroll
        for (int r = 0; r < 8; r++)
            if (m1v[r]) cm = fmaxf(cm, c[r][q]);
        redC[8 * q + tx][ty] = cm;
    }
    __syncthreads();
    if (tid < BJ) {
        float m = NEGF;
#pragma unroll
        for (int t = 0; t < 16; t++) m = fmaxf(m, redC[tid][t]);
        atomicMax(&g_colmax[b * S + j0 + tid], ordf(m));
    }
}

// ---------------- kernel 4: final masked sums ----------------
__global__ void k_final(const int* __restrict__ mask1, const int* __restrict__ mask2,
                        float* __restrict__ out) {
    __shared__ float ssum[256];
    __shared__ int   scnt[256];
    const int b = blockIdx.x;
    const int tid = threadIdx.x;

    float s = 0.f;
    int   n = 0;
    for (int i = tid; i < S; i += 256) {
        int m1 = mask1[b * S + i];
        if (m1) s += deord(g_rowmax[b * S + i]);
        n += m1;
        int m2 = mask2[b * S + i];
        if (m2) s += deord(g_colmax[b * S + i]);
        n += m2;
    }
    ssum[tid] = s; scnt[tid] = n;
    __syncthreads();
    for (int o = 128; o > 0; o >>= 1) {
        if (tid < o) { ssum[tid] += ssum[tid + o]; scnt[tid] += scnt[tid + o]; }
        __syncthreads();
    }
    if (tid == 0) out[b] = ssum[0] / (float)scnt[0];
}

// ---------------- launch ----------------
extern "C" void kernel_launch(void* const* d_in, const int* in_sizes, int n_in,
                              void* d_out, int out_size) {
    const float* emb1  = (const float*)d_in[0];
    const float* emb2  = (const float*)d_in[1];
    const int*   mask1 = (const int*)d_in[2];
    const int*   mask2 = (const int*)d_in[3];
    float*       out   = (float*)d_out;

    float* inv1p; float* inv2p;
    cudaGetSymbolAddress((void**)&inv1p, g_inv1);
    cudaGetSymbolAddress((void**)&inv2p, g_inv2);

    // 1) inverse norms (one warp per row)
    k_inv<<<(B * S) / 8, 256>>>(emb1, inv1p);
    k_inv<<<(B * S) / 8, 256>>>(emb2, inv2p);

    // 2) init max buffers with ordf(-1e9f) = 0xB19194D7
    k_init<<<(B * S + 255) / 256, 256>>>((int)0xB19194D7);

    // 3) sim tiles: grid (j-tiles=8, i-tiles=4, batch=64) = 2048 CTAs
    dim3 grid(S / BJ, S / BI, B);
    k_sim<<<grid, 128>>>(emb1, emb2, mask1, mask2);

    // 4) final
    k_final<<<B, 256>>>(mask1, mask2, out);
}

// round 5
// speedup vs baseline: 4.5221x; 2.2330x over previous
#include <cuda_runtime.h>
#include <cuda_bf16.h>
#include <cstdint>

// Problem shape (fixed by the dataset)
#define B 64
#define S 512
#define DD 512

#define NEG_ORD ((int)0xB19194D7)   // ordf(-1e9f)
#define NEGF (-1e9f)

// ---------------- global scratch (no allocations allowed) ----------------
__device__ __align__(16) __nv_bfloat16 g_A_hi[(size_t)B * S * DD];
__device__ __align__(16) __nv_bfloat16 g_A_lo[(size_t)B * S * DD];
__device__ __align__(16) __nv_bfloat16 g_B_hi[(size_t)B * S * DD];
__device__ __align__(16) __nv_bfloat16 g_B_lo[(size_t)B * S * DD];
__device__ int g_rowmax[B * S];
__device__ int g_colmax[B * S];

// ---------------- helpers ----------------
__device__ __forceinline__ int ordf(float f) {
    int i = __float_as_int(f);
    return (i >= 0) ? i : (i ^ 0x7FFFFFFF);
}
__device__ __forceinline__ float deord(int s) {
    return __int_as_float((s >= 0) ? s : (s ^ 0x7FFFFFFF));
}
__device__ __forceinline__ uint32_t smem_u32(const void* p) {
    uint32_t a;
    asm("{ .reg .u64 t; cvta.to.shared.u64 t, %1; cvt.u32.u64 %0, t; }" : "=r"(a) : "l"(p));
    return a;
}

#define CP_ASYNC16(dst, src) \
    asm volatile("cp.async.cg.shared.global [%0], [%1], 16;" :: "r"(dst), "l"(src) : "memory")
#define CP_COMMIT()  asm volatile("cp.async.commit_group;" ::: "memory")
#define CP_WAIT(n)   asm volatile("cp.async.wait_group %0;" :: "n"(n) : "memory")

#define LDSM_X4(r0, r1, r2, r3, addr) \
    asm volatile("ldmatrix.sync.aligned.m8n8.x4.shared.b16 {%0,%1,%2,%3}, [%4];" \
                 : "=r"(r0), "=r"(r1), "=r"(r2), "=r"(r3) : "r"(addr))

#define MMA_BF16(c, a, b0v, b1v) \
    asm volatile("mma.sync.aligned.m16n8k16.row.col.f32.bf16.bf16.f32 " \
                 "{%0,%1,%2,%3}, {%4,%5,%6,%7}, {%8,%9}, {%0,%1,%2,%3};" \
                 : "+f"((c)[0]), "+f"((c)[1]), "+f"((c)[2]), "+f"((c)[3]) \
                 : "r"((a)[0]), "r"((a)[1]), "r"((a)[2]), "r"((a)[3]), "r"(b0v), "r"(b1v))

// ---------------- prep: normalize + bf16 hi/lo split ----------------
// One warp per row. SIDE 0: e1 -> g_A_* + init g_rowmax. SIDE 1: e2 -> g_B_* + init g_colmax.
template <int SIDE>
__global__ void k_prep(const float* __restrict__ in) {
    int row  = (blockIdx.x * blockDim.x + threadIdx.x) >> 5;
    int lane = threadIdx.x & 31;
    if (row >= B * S) return;
    const float4* rp = (const float4*)(in + (size_t)row * DD);

    float4 v0a = rp[2 * lane],        v0b = rp[2 * lane + 1];
    float4 v1a = rp[2 * (lane + 32)], v1b = rp[2 * (lane + 32) + 1];

    float ss = 0.f;
    ss = fmaf(v0a.x, v0a.x, ss); ss = fmaf(v0a.y, v0a.y, ss);
    ss = fmaf(v0a.z, v0a.z, ss); ss = fmaf(v0a.w, v0a.w, ss);
    ss = fmaf(v0b.x, v0b.x, ss); ss = fmaf(v0b.y, v0b.y, ss);
    ss = fmaf(v0b.z, v0b.z, ss); ss = fmaf(v0b.w, v0b.w, ss);
    ss = fmaf(v1a.x, v1a.x, ss); ss = fmaf(v1a.y, v1a.y, ss);
    ss = fmaf(v1a.z, v1a.z, ss); ss = fmaf(v1a.w, v1a.w, ss);
    ss = fmaf(v1b.x, v1b.x, ss); ss = fmaf(v1b.y, v1b.y, ss);
    ss = fmaf(v1b.z, v1b.z, ss); ss = fmaf(v1b.w, v1b.w, ss);
#pragma unroll
    for (int o = 16; o > 0; o >>= 1) ss += __shfl_xor_sync(0xFFFFFFFFu, ss, o);
    float inv = 1.0f / fmaxf(sqrtf(ss), 1e-8f);

    __nv_bfloat16* dhi = (SIDE == 0) ? g_A_hi : g_B_hi;
    __nv_bfloat16* dlo = (SIDE == 0) ? g_A_lo : g_B_lo;
    if (lane == 0) {
        if (SIDE == 0) g_rowmax[row] = NEG_ORD; else g_colmax[row] = NEG_ORD;
    }

#pragma unroll
    for (int half = 0; half < 2; half++) {
        float x[8];
        if (half == 0) {
            x[0] = v0a.x; x[1] = v0a.y; x[2] = v0a.z; x[3] = v0a.w;
            x[4] = v0b.x; x[5] = v0b.y; x[6] = v0b.z; x[7] = v0b.w;
        } else {
            x[0] = v1a.x; x[1] = v1a.y; x[2] = v1a.z; x[3] = v1a.w;
            x[4] = v1b.x; x[5] = v1b.y; x[6] = v1b.z; x[7] = v1b.w;
        }
        __nv_bfloat16 h[8], l[8];
#pragma unroll
        for (int u = 0; u < 8; u++) {
            float v = x[u] * inv;
            h[u] = __float2bfloat16(v);
            l[u] = __float2bfloat16(v - __bfloat162float(h[u]));
        }
        size_t idx = (size_t)row * DD + (size_t)(lane + 32 * half) * 8;
        *(uint4*)(dhi + idx) = *(uint4*)h;
        *(uint4*)(dlo + idx) = *(uint4*)l;
    }
}

// ---------------- GEMM: bf16 mma.sync split-precision + masked row/col max ----------------
// CTA 256 threads (8 warps), tile 128(i) x 128(j), k-chunk 64, 2-stage cp.async pipeline.
// Warp w: rows 32*(w&3) .. +32, cols 64*(w>>2) .. +64. Warp tile 32x64: 2 m-frags x 8 n-frags.
#define KCH 64
#define NCHUNK (DD / KCH)
#define STAGE_BYTES 65536
#define OFF_AHI 0
#define OFF_ALO 16384
#define OFF_BHI 32768
#define OFF_BLO 49152

__global__ __launch_bounds__(256, 1) void k_gemm(const int* __restrict__ mask1,
                                                 const int* __restrict__ mask2) {
    extern __shared__ __align__(1024) char smem[];
    __shared__ int m1s[128], m2s[128];

    const uint32_t sb = smem_u32(smem);
    const int tid  = threadIdx.x;
    const int wid  = tid >> 5;
    const int lane = tid & 31;
    const int b  = blockIdx.z;
    const int ib = blockIdx.y;
    const int jb = blockIdx.x;
    const int i0 = ib * 128;
    const int j0 = jb * 128;

    if (tid < 128) m1s[tid] = mask1[b * S + i0 + tid];
    else           m2s[tid - 128] = mask2[b * S + j0 + (tid - 128)];

    const __nv_bfloat16* pAhi = g_A_hi + ((size_t)b * S + i0) * DD;
    const __nv_bfloat16* pAlo = g_A_lo + ((size_t)b * S + i0) * DD;
    const __nv_bfloat16* pBhi = g_B_hi + ((size_t)b * S + j0) * DD;
    const __nv_bfloat16* pBlo = g_B_lo + ((size_t)b * S + j0) * DD;

    // loader mapping: granule G = tid + 256*u (u<4): row = G>>3, kg = G&7
    int lrow[4], lkg[4];
    uint32_t ldst[4];
#pragma unroll
    for (int u = 0; u < 4; u++) {
        int G = tid + 256 * u;
        lrow[u] = G >> 3;
        lkg[u]  = G & 7;
        ldst[u] = (uint32_t)(lrow[u] * 128 + ((lkg[u] ^ (lrow[u] & 7)) * 16));
    }

    auto issue_chunk = [&](int kc, int st) {
        uint32_t stg = sb + st * STAGE_BYTES;
        size_t kbase = (size_t)kc * KCH;
#pragma unroll
        for (int u = 0; u < 4; u++) {
            size_t so = (size_t)lrow[u] * DD + kbase + lkg[u] * 8;
            CP_ASYNC16(stg + OFF_AHI + ldst[u], pAhi + so);
            CP_ASYNC16(stg + OFF_ALO + ldst[u], pAlo + so);
            CP_ASYNC16(stg + OFF_BHI + ldst[u], pBhi + so);
            CP_ASYNC16(stg + OFF_BLO + ldst[u], pBlo + so);
        }
    };

    float acc[2][8][4];
#pragma unroll
    for (int mi = 0; mi < 2; mi++)
#pragma unroll
        for (int nj = 0; nj < 8; nj++)
#pragma unroll
            for (int r = 0; r < 4; r++) acc[mi][nj][r] = 0.f;

    const int wr = (wid & 3) * 32;
    const int wc = (wid >> 2) * 64;

    // ldmatrix lane address components
    // A x4 at (mb, kg0): row = mb + (lane&7) + 8*((lane>>3)&1), kg = kg0 + (lane>>4)
    const int a_r = (lane & 7) + 8 * ((lane >> 3) & 1);
    const int a_k = lane >> 4;
    // B x4 at (nb, kg0): row = nb + (lane&7) + 8*(lane>>4), kg = kg0 + ((lane>>3)&1)
    const int b_r = (lane & 7) + 8 * (lane >> 4);
    const int b_k = (lane >> 3) & 1;

    issue_chunk(0, 0);
    CP_COMMIT();

#pragma unroll 1
    for (int t = 0; t < NCHUNK; t++) {
        if (t < NCHUNK - 1) {
            issue_chunk(t + 1, (t + 1) & 1);
            CP_COMMIT();
            CP_WAIT(1);
        } else {
            CP_WAIT(0);
        }
        __syncthreads();

        uint32_t stg = sb + (t & 1) * STAGE_BYTES;
#pragma unroll
        for (int ks = 0; ks < 4; ks++) {
            const int kg0 = ks * 2;
            uint32_t ah[2][4], al[2][4], bh[4][4], bl[4][4];
#pragma unroll
            for (int mi = 0; mi < 2; mi++) {
                int row = wr + 16 * mi + a_r;
                uint32_t ad = stg + (uint32_t)(row * 128 + (((kg0 + a_k) ^ (row & 7)) * 16));
                LDSM_X4(ah[mi][0], ah[mi][1], ah[mi][2], ah[mi][3], ad + OFF_AHI);
                LDSM_X4(al[mi][0], al[mi][1], al[mi][2], al[mi][3], ad + OFF_ALO);
            }
#pragma unroll
            for (int nb = 0; nb < 4; nb++) {
                int row = wc + 16 * nb + b_r;
                uint32_t bd = stg + (uint32_t)(row * 128 + (((kg0 + b_k) ^ (row & 7)) * 16));
                LDSM_X4(bh[nb][0], bh[nb][1], bh[nb][2], bh[nb][3], bd + OFF_BHI);
                LDSM_X4(bl[nb][0], bl[nb][1], bl[nb][2], bl[nb][3], bd + OFF_BLO);
            }
#pragma unroll
            for (int mi = 0; mi < 2; mi++)
#pragma unroll
                for (int nb = 0; nb < 4; nb++) {
                    MMA_BF16(acc[mi][2 * nb],     ah[mi], bh[nb][0], bh[nb][1]);
                    MMA_BF16(acc[mi][2 * nb + 1], ah[mi], bh[nb][2], bh[nb][3]);
                    MMA_BF16(acc[mi][2 * nb],     al[mi], bh[nb][0], bh[nb][1]);
                    MMA_BF16(acc[mi][2 * nb + 1], al[mi], bh[nb][2], bh[nb][3]);
                    MMA_BF16(acc[mi][2 * nb],     ah[mi], bl[nb][0], bl[nb][1]);
                    MMA_BF16(acc[mi][2 * nb + 1], ah[mi], bl[nb][2], bl[nb][3]);
                }
        }
        __syncthreads();
    }

    // -------- epilogue: masked row/col maxes from D fragments --------
    const int g  = lane >> 2;
    const int tg = lane & 3;

    // thread's column masks (16 cols) and row masks (4 rows)
    int cmask[8][2];
#pragma unroll
    for (int nj = 0; nj < 8; nj++) {
        cmask[nj][0] = m2s[wc + 8 * nj + 2 * tg];
        cmask[nj][1] = m2s[wc + 8 * nj + 2 * tg + 1];
    }
    int rmask[2][2];
#pragma unroll
    for (int mi = 0; mi < 2; mi++) {
        rmask[mi][0] = m1s[wr + 16 * mi + g];
        rmask[mi][1] = m1s[wr + 16 * mi + g + 8];
    }

    // row maxes
#pragma unroll
    for (int mi = 0; mi < 2; mi++)
#pragma unroll
        for (int p = 0; p < 2; p++) {
            float rm = NEGF;
#pragma unroll
            for (int nj = 0; nj < 8; nj++) {
                if (cmask[nj][0]) rm = fmaxf(rm, acc[mi][nj][2 * p]);
                if (cmask[nj][1]) rm = fmaxf(rm, acc[mi][nj][2 * p + 1]);
            }
            rm = fmaxf(rm, __shfl_xor_sync(0xFFFFFFFFu, rm, 1));
            rm = fmaxf(rm, __shfl_xor_sync(0xFFFFFFFFu, rm, 2));
            if (tg == 0)
                atomicMax(&g_rowmax[b * S + i0 + wr + 16 * mi + g + 8 * p], ordf(rm));
        }

    // col maxes
#pragma unroll
    for (int nj = 0; nj < 8; nj++)
#pragma unroll
        for (int q = 0; q < 2; q++) {
            float cm = NEGF;
#pragma unroll
            for (int mi = 0; mi < 2; mi++) {
                if (rmask[mi][0]) cm = fmaxf(cm, acc[mi][nj][q]);
                if (rmask[mi][1]) cm = fmaxf(cm, acc[mi][nj][2 + q]);
            }
            cm = fmaxf(cm, __shfl_xor_sync(0xFFFFFFFFu, cm, 4));
            cm = fmaxf(cm, __shfl_xor_sync(0xFFFFFFFFu, cm, 8));
            cm = fmaxf(cm, __shfl_xor_sync(0xFFFFFFFFu, cm, 16));
            if (g == 0)
                atomicMax(&g_colmax[b * S + j0 + wc + 8 * nj + 2 * tg + q], ordf(cm));
        }
}

// ---------------- final masked sums ----------------
__global__ void k_final(const int* __restrict__ mask1, const int* __restrict__ mask2,
                        float* __restrict__ out) {
    __shared__ float ssum[256];
    __shared__ int   scnt[256];
    const int b = blockIdx.x;
    const int tid = threadIdx.x;

    float s = 0.f;
    int   n = 0;
    for (int i = tid; i < S; i += 256) {
        int m1 = mask1[b * S + i];
        if (m1) s += deord(g_rowmax[b * S + i]);
        n += m1;
        int m2 = mask2[b * S + i];
        if (m2) s += deord(g_colmax[b * S + i]);
        n += m2;
    }
    ssum[tid] = s; scnt[tid] = n;
    __syncthreads();
    for (int o = 128; o > 0; o >>= 1) {
        if (tid < o) { ssum[tid] += ssum[tid + o]; scnt[tid] += scnt[tid + o]; }
        __syncthreads();
    }
    if (tid == 0) out[b] = ssum[0] / (float)scnt[0];
}

// ---------------- launch ----------------
extern "C" void kernel_launch(void* const* d_in, const int* in_sizes, int n_in,
                              void* d_out, int out_size) {
    const float* emb1  = (const float*)d_in[0];
    const float* emb2  = (const float*)d_in[1];
    const int*   mask1 = (const int*)d_in[2];
    const int*   mask2 = (const int*)d_in[3];
    float*       out   = (float*)d_out;

    static bool attr_set = false;
    if (!attr_set) {
        cudaFuncSetAttribute(k_gemm, cudaFuncAttributeMaxDynamicSharedMemorySize, 2 * STAGE_BYTES);
        attr_set = true;
    }

    // 1) prep (one warp per row)
    k_prep<0><<<(B * S) / 8, 256>>>(emb1);
    k_prep<1><<<(B * S) / 8, 256>>>(emb2);

    // 2) GEMM + masked maxes: grid (jb=4, ib=4, b=64) = 1024 CTAs
    dim3 grid(S / 128, S / 128, B);
    k_gemm<<<grid, 256, 2 * STAGE_BYTES>>>(mask1, mask2);

    // 3) final
    k_final<<<B, 256>>>(mask1, mask2, out);
}